// round 7
// baseline (speedup 1.0000x reference)
#include <cuda_runtime.h>
#include <cstdint>

// Problem dims (fixed by the dataset)
#define BATCH 32
#define F_IN  512
#define T_LEN 256
#define HID   1024
#define OUTD  128

#define N_CHAINS (BATCH * HID)                  // 32768 LIF chains per layer

// Output layout (floats): spikes0, spikes1, readouts0, readouts1, voltages0, voltages1, counts[2]
#define SOFF0 ((size_t)0)
#define SOFF1 ((size_t)8388608)
#define ROFF0 ((size_t)16777216)
#define ROFF1 ((size_t)17825792)
#define VOFF0 ((size_t)18874368)
#define VOFF1 ((size_t)27262976)
#define CNTOFF ((size_t)35651584)

// ---------------- device scratch ----------------
__device__ float  g_s [(size_t)BATCH * 4 * HID  * T_LEN];    // hidden plane sums (134MB)
__device__ float  g_sr[(size_t)BATCH * 4 * OUTD * T_LEN];    // readout plane sums (16.8MB)
__device__ int8_t g_bT[(size_t)BATCH * T_LEN * HID];         // transposed s8 B operand (reused)
__device__ int8_t g_w1i [4 * HID * F_IN];                    // W1 digit planes
__device__ int8_t g_w2r1[4 * HID * HID + 4 * OUTD * HID];    // W2 planes ++ R1 planes (stacked)
__device__ int8_t g_r2i [4 * OUTD * HID];                    // R2 digit planes
__device__ unsigned long long g_cnt[2];

// ---------------- baseline-PTX helpers (valid on compute_103) ----------------
__device__ __forceinline__ uint32_t smem_u32(const void* p) {
    uint32_t a;
    asm("{ .reg .u64 t; cvta.to.shared.u64 t, %1; cvt.u32.u64 %0, t; }" : "=r"(a) : "l"(p));
    return a;
}

__device__ __forceinline__ void cp_async16(uint32_t dst, const void* src) {
    asm volatile("cp.async.ca.shared.global [%0], [%1], 16;" :: "r"(dst), "l"(src));
}
#define CP_COMMIT() asm volatile("cp.async.commit_group;" ::: "memory")
#define CP_WAIT0()  asm volatile("cp.async.wait_group 0;" ::: "memory")

__device__ __forceinline__ void ldsm_x4(uint32_t r[4], uint32_t addr) {
    asm volatile("ldmatrix.sync.aligned.m8n8.x4.shared.b16 {%0,%1,%2,%3}, [%4];"
        : "=r"(r[0]), "=r"(r[1]), "=r"(r[2]), "=r"(r[3]) : "r"(addr));
}

// int8 MMA, exact s32 accumulate: D = A(16x32,s8) * B(32x8,s8)^T + D
__device__ __forceinline__ void mma_s8(int* d, const uint32_t* a, uint32_t b0, uint32_t b1) {
    asm volatile(
        "mma.sync.aligned.m16n8k32.row.col.s32.s8.s8.s32 "
        "{%0,%1,%2,%3}, {%4,%5,%6,%7}, {%8,%9}, {%0,%1,%2,%3};"
        : "+r"(d[0]), "+r"(d[1]), "+r"(d[2]), "+r"(d[3])
        : "r"(a[0]), "r"(a[1]), "r"(a[2]), "r"(a[3]), "r"(b0), "r"(b1));
}

// ---------------- small kernels ----------------
__global__ void init_counts_kernel() { g_cnt[0] = 0ull; g_cnt[1] = 0ull; }

// Exact 4-digit base-128 fixed-point split at scale 2^28.
// q = rint(w*2^28); q = c0*2^21 + c1*2^14 + c2*2^7 + c3 exactly, |ci| <= 64.
__global__ void wprep_kernel(const float* __restrict__ W, int8_t* __restrict__ out, int n) {
    for (int i = blockIdx.x * blockDim.x + threadIdx.x; i < n; i += gridDim.x * blockDim.x) {
        double wd = (double)W[i] * 268435456.0;   // 2^28, exact
        long long ql = llrint(wd);
        int qi = (int)ql;
        int c0 = (qi + (1 << 20)) >> 21;
        int r  = qi - (c0 << 21);
        int c1 = (r + (1 << 13)) >> 14;
        r     -= (c1 << 14);
        int c2 = (r + (1 << 6)) >> 7;
        r     -= (c2 << 7);
        out[i]         = (int8_t)c0;
        out[n + i]     = (int8_t)c1;
        out[2 * n + i] = (int8_t)c2;
        out[3 * n + i] = (int8_t)r;
    }
}

// in: fp32 [B, F, T] (values exactly 0/1) -> out: int8 [B, T, F]
__global__ void transpose_s8_kernel(const float* __restrict__ in,
                                    int8_t* __restrict__ outT, int F) {
    __shared__ float tile[32][33];
    const int b = blockIdx.z;
    const int t0 = blockIdx.x * 32, f0 = blockIdx.y * 32;
    const float* inp = in + ((size_t)b * F + f0) * T_LEN + t0;
#pragma unroll
    for (int i = 0; i < 4; i++)
        tile[threadIdx.y + i * 8][threadIdx.x] = inp[(size_t)(threadIdx.y + i * 8) * T_LEN + threadIdx.x];
    __syncthreads();
    int8_t* op = outT + ((size_t)b * T_LEN + t0) * F + f0;
#pragma unroll
    for (int i = 0; i < 4; i++)
        op[(size_t)(threadIdx.y + i * 8) * F + threadIdx.x] =
            (int8_t)(tile[threadIdx.x][threadIdx.y + i * 8] >= 0.5f ? 1 : 0);
}

// ---------------- exact int8 tensor-core plane-GEMM (stacked planes in M) ----------------
// S[b, row, t] = sum_k A[row, k] * Bt[b, t, k]   (rows span stacked digit planes)
// A: [Mtot][K] s8.  Bt: [B][T_LEN][K] s8 (0/1).  Sums <= 2^16, exact in s32 and fp32.
// Rows < Mhid go to Sh [B][Mhid][T]; remaining Mr rows go to Sr [B][Mr][T].
// CTA tile 128(M) x 128(N), K chunk 64; 8 warps = 4(M) x 2(N), warp tile 32x64.
__global__ __launch_bounds__(256)
void imma_gemm_kernel(const int8_t* __restrict__ A,
                      const int8_t* __restrict__ Bt,
                      float* __restrict__ Sh, float* __restrict__ Sr,
                      int Mhid, int Mr, int K)
{
    constexpr int ROWB  = 80;                  // 64B data + 16B pad
    constexpr int BOFF  = 128 * ROWB;          // 10240
    constexpr int STAGE = 2 * BOFF;            // 20480

    extern __shared__ __align__(16) char smem[];
    const uint32_t uS = smem_u32(smem);

    const int tid  = threadIdx.x;
    const int wid  = tid >> 5;
    const int lane = tid & 31;
    const int wm   = wid & 3;          // warp m-group (32 rows)
    const int wn   = wid >> 2;         // warp n-group (64 cols)

    const int m0 = blockIdx.y * 128;
    const int n0 = blockIdx.x * 128;
    const int b  = blockIdx.z;

    const int8_t* Brow = Bt + ((size_t)b * T_LEN + n0) * K;

    // A/B tiles: 128 rows x 4 x 16B = 512 chunks -> 2 per thread each.
    int cr[2], cq[2];
#pragma unroll
    for (int u = 0; u < 2; u++) { cr[u] = (tid + u * 256) >> 2; cq[u] = (tid + u * 256) & 3; }

    const uint32_t lmoff = (uint32_t)((lane & 15) * ROWB + (lane >> 4) * 16);

    int acc[2][8][4];
#pragma unroll
    for (int ii = 0; ii < 2; ii++)
#pragma unroll
        for (int jj = 0; jj < 8; jj++)
#pragma unroll
            for (int r = 0; r < 4; r++) acc[ii][jj][r] = 0;

    const int NKC = K / 64;

    // ---- prologue: stage 0 ----
#pragma unroll
    for (int u = 0; u < 2; u++) {
        cp_async16(uS + cr[u] * ROWB + cq[u] * 16,
                   A + (size_t)(m0 + cr[u]) * K + cq[u] * 16);
        cp_async16(uS + BOFF + cr[u] * ROWB + cq[u] * 16,
                   Brow + (size_t)cr[u] * K + cq[u] * 16);
    }
    CP_COMMIT();

    for (int kc = 0; kc < NKC; kc++) {
        const uint32_t cur = (uint32_t)(kc & 1) * STAGE;
        CP_WAIT0();
        __syncthreads();

        if (kc + 1 < NKC) {
            const uint32_t nxt = (uint32_t)((kc + 1) & 1) * STAGE;
            const int kB = (kc + 1) * 64;
#pragma unroll
            for (int u = 0; u < 2; u++) {
                cp_async16(uS + nxt + cr[u] * ROWB + cq[u] * 16,
                           A + (size_t)(m0 + cr[u]) * K + kB + cq[u] * 16);
                cp_async16(uS + nxt + BOFF + cr[u] * ROWB + cq[u] * 16,
                           Brow + (size_t)cr[u] * K + kB + cq[u] * 16);
            }
            CP_COMMIT();
        }

        // 2 k32-steps per 64-byte chunk
#pragma unroll
        for (int ks = 0; ks < 2; ks++) {
            const uint32_t koff = cur + (uint32_t)(ks * 32) + lmoff;

            uint32_t bf[4][4];
#pragma unroll
            for (int j2 = 0; j2 < 4; j2++)
                ldsm_x4(bf[j2], uS + BOFF + (uint32_t)((wn * 64 + j2 * 16) * ROWB) + koff);

#pragma unroll
            for (int ii = 0; ii < 2; ii++) {
                uint32_t af[4];
                ldsm_x4(af, uS + (uint32_t)((wm * 32 + ii * 16) * ROWB) + koff);
#pragma unroll
                for (int j2 = 0; j2 < 4; j2++) {
                    mma_s8(acc[ii][2 * j2 + 0], af, bf[j2][0], bf[j2][2]);
                    mma_s8(acc[ii][2 * j2 + 1], af, bf[j2][1], bf[j2][3]);
                }
            }
        }
        __syncthreads();
    }

    // ---- epilogue: exact s32 -> fp32 plane sums ----
    float* dst;
    if (m0 < Mhid) dst = Sh + ((size_t)b * Mhid + m0) * T_LEN;
    else           dst = Sr + ((size_t)b * Mr + (m0 - Mhid)) * T_LEN;

#pragma unroll
    for (int ii = 0; ii < 2; ii++) {
        const int rloc = wm * 32 + ii * 16 + (lane >> 2);
        float* d0 = dst + (size_t)rloc * T_LEN + n0 + wn * 64 + (lane & 3) * 2;
#pragma unroll
        for (int jj = 0; jj < 8; jj++) {
            *(float2*)(d0 + jj * 8) =
                make_float2((float)acc[ii][jj][0], (float)acc[ii][jj][1]);
            *(float2*)(d0 + 8 * T_LEN + jj * 8) =
                make_float2((float)acc[ii][jj][2], (float)acc[ii][jj][3]);
        }
    }
}

// ---------------- digit fold (4 planes, base 128, scale 2^28; exact in double) ----------------
__device__ __forceinline__ float fold4(float a, float b, float c, float d) {
    return (float)(((double)a * 2097152.0 + (double)b * 16384.0 +
                    (double)c * 128.0 + (double)d) * (1.0 / 268435456.0));
}

// ---------------- LIF with on-the-fly digit fold ----------------
__global__ __launch_bounds__(256)
void lif_fold_kernel(float* __restrict__ v_out, float* __restrict__ s_out, int layer)
{
    const int idx = blockIdx.x * blockDim.x + threadIdx.x;   // chain = b*HID + h
    const int b = idx / HID, h = idx % HID;
    const float4* __restrict__ p0 = (const float4*)(g_s + ((size_t)b * 4 * HID + 0 * HID + h) * T_LEN);
    const float4* __restrict__ p1 = (const float4*)(g_s + ((size_t)b * 4 * HID + 1 * HID + h) * T_LEN);
    const float4* __restrict__ p2 = (const float4*)(g_s + ((size_t)b * 4 * HID + 2 * HID + h) * T_LEN);
    const float4* __restrict__ p3 = (const float4*)(g_s + ((size_t)b * 4 * HID + 3 * HID + h) * T_LEN);
    float4* __restrict__ vp4 = (float4*)(v_out + (size_t)idx * T_LEN);
    float4* __restrict__ sp4 = (float4*)(s_out + (size_t)idx * T_LEN);

    float cur = 0.0f, volt = 0.0f;
    unsigned cnt = 0;

#pragma unroll 4
    for (int t4 = 0; t4 < T_LEN / 4; t4++) {
        const float4 a = p0[t4], bb = p1[t4], c = p2[t4], d = p3[t4];
        float4 z;
        z.x = fold4(a.x, bb.x, c.x, d.x);
        z.y = fold4(a.y, bb.y, c.y, d.y);
        z.z = fold4(a.z, bb.z, c.z, d.z);
        z.w = fold4(a.w, bb.w, c.w, d.w);
        float4 v, s;
        cur = 0.75f * cur + z.x;  volt = 0.97f * volt + cur;  v.x = volt;
        { bool sp = volt >= 1.25f; s.x = sp ? 1.0f : 0.0f; cnt += (unsigned)sp; if (sp) volt = 0.0f; }
        cur = 0.75f * cur + z.y;  volt = 0.97f * volt + cur;  v.y = volt;
        { bool sp = volt >= 1.25f; s.y = sp ? 1.0f : 0.0f; cnt += (unsigned)sp; if (sp) volt = 0.0f; }
        cur = 0.75f * cur + z.z;  volt = 0.97f * volt + cur;  v.z = volt;
        { bool sp = volt >= 1.25f; s.z = sp ? 1.0f : 0.0f; cnt += (unsigned)sp; if (sp) volt = 0.0f; }
        cur = 0.75f * cur + z.w;  volt = 0.97f * volt + cur;  v.w = volt;
        { bool sp = volt >= 1.25f; s.w = sp ? 1.0f : 0.0f; cnt += (unsigned)sp; if (sp) volt = 0.0f; }
        vp4[t4] = v;
        sp4[t4] = s;
    }

    __shared__ unsigned red[256];
    red[threadIdx.x] = cnt;
    __syncthreads();
#pragma unroll
    for (int off = 128; off > 0; off >>= 1) {
        if (threadIdx.x < off) red[threadIdx.x] += red[threadIdx.x + off];
        __syncthreads();
    }
    if (threadIdx.x == 0)
        atomicAdd(&g_cnt[layer], (unsigned long long)red[0]);
}

// fold readout planes: Sr [B][4*OUTD][T] -> r [B][OUTD][T]
__global__ __launch_bounds__(256)
void fold_readout_kernel(float* __restrict__ rout)
{
    const int i = blockIdx.x * blockDim.x + threadIdx.x;   // over B*OUTD*T/4
    const int per = OUTD * T_LEN / 4;
    const int b = i / per, rem = i % per;
    const float4* base = (const float4*)(g_sr + (size_t)b * 4 * OUTD * T_LEN);
    const float4 a  = base[0 * per + rem];
    const float4 bb = base[1 * per + rem];
    const float4 c  = base[2 * per + rem];
    const float4 d  = base[3 * per + rem];
    float4 r;
    r.x = fold4(a.x, bb.x, c.x, d.x);
    r.y = fold4(a.y, bb.y, c.y, d.y);
    r.z = fold4(a.z, bb.z, c.z, d.z);
    r.w = fold4(a.w, bb.w, c.w, d.w);
    ((float4*)(rout + (size_t)b * OUTD * T_LEN))[rem] = r;
}

__global__ void finalize_counts_kernel(float* __restrict__ out)
{
    const double total = (double)((size_t)BATCH * HID * T_LEN);
    out[0] = (float)((double)g_cnt[0] / total);
    out[1] = (float)((double)g_cnt[1] / total);
}

// ---------------- launch ----------------
extern "C" void kernel_launch(void* const* d_in, const int* in_sizes, int n_in,
                              void* d_out, int out_size)
{
    const float* spike = (const float*)d_in[0]; // [32, 512, 256]
    const float* W1    = (const float*)d_in[1]; // [1024, 512]
    const float* W2    = (const float*)d_in[2]; // [1024, 1024]
    const float* R1    = (const float*)d_in[3]; // [128, 1024]
    const float* R2    = (const float*)d_in[4]; // [128, 1024]
    float* out = (float*)d_out;

    float *sptr, *srptr;
    int8_t *bT, *w1i, *w2r1, *r2i;
    cudaGetSymbolAddress((void**)&sptr,  g_s);
    cudaGetSymbolAddress((void**)&srptr, g_sr);
    cudaGetSymbolAddress((void**)&bT,    g_bT);
    cudaGetSymbolAddress((void**)&w1i,   g_w1i);
    cudaGetSymbolAddress((void**)&w2r1,  g_w2r1);
    cudaGetSymbolAddress((void**)&r2i,   g_r2i);

    float* s0 = out + SOFF0;
    float* s1 = out + SOFF1;
    float* r0 = out + ROFF0;
    float* r1 = out + ROFF1;
    float* v0 = out + VOFF0;
    float* v1 = out + VOFF1;

    const int SMEM = 2 * 20480;   // 40960
    cudaFuncSetAttribute(imma_gemm_kernel, cudaFuncAttributeMaxDynamicSharedMemorySize, SMEM);

    init_counts_kernel<<<1, 1>>>();

    // Weight digit-plane prep (deterministic, every call)
    wprep_kernel<<<256, 256>>>(W1, w1i, HID * F_IN);
    wprep_kernel<<<256, 256>>>(W2, w2r1, HID * HID);
    wprep_kernel<<<128, 256>>>(R1, w2r1 + 4 * HID * HID, OUTD * HID);
    wprep_kernel<<<128, 256>>>(R2, r2i, OUTD * HID);

    // x^T s8
    transpose_s8_kernel<<<dim3(T_LEN / 32, F_IN / 32, BATCH), dim3(32, 8)>>>(spike, bT, F_IN);

    // Layer 1 synapse plane sums: S = W1planes @ x  (M=4096, K=512)
    imma_gemm_kernel<<<dim3(T_LEN / 128, 4 * HID / 128, BATCH), 256, SMEM>>>(
        w1i, bT, sptr, srptr, 4 * HID, 0, F_IN);
    lif_fold_kernel<<<N_CHAINS / 256, 256>>>(v0, s0, 0);

    // s0^T s8
    transpose_s8_kernel<<<dim3(T_LEN / 32, HID / 32, BATCH), dim3(32, 8)>>>(s0, bT, HID);

    // Layer 2 synapse + readout 1 in ONE stacked GEMM (M = 4096 + 512 = 4608, K=1024)
    imma_gemm_kernel<<<dim3(T_LEN / 128, (4 * HID + 4 * OUTD) / 128, BATCH), 256, SMEM>>>(
        w2r1, bT, sptr, srptr, 4 * HID, 4 * OUTD, HID);

    lif_fold_kernel<<<N_CHAINS / 256, 256>>>(v1, s1, 1);
    fold_readout_kernel<<<(BATCH * OUTD * T_LEN / 4) / 256, 256>>>(r0);

    // s1^T s8 ; readout 2 (M=512, K=1024)
    transpose_s8_kernel<<<dim3(T_LEN / 32, HID / 32, BATCH), dim3(32, 8)>>>(s1, bT, HID);
    imma_gemm_kernel<<<dim3(T_LEN / 128, 4 * OUTD / 128, BATCH), 256, SMEM>>>(
        r2i, bT, sptr, srptr, 0, 4 * OUTD, HID);
    fold_readout_kernel<<<(BATCH * OUTD * T_LEN / 4) / 256, 256>>>(r1);

    finalize_counts_kernel<<<1, 1>>>(out + CNTOFF);
}

// round 8
// speedup vs baseline: 1.9279x; 1.9279x over previous
#include <cuda_runtime.h>
#include <cuda_fp16.h>
#include <cstdint>

// Problem dims (fixed by the dataset)
#define BATCH 32
#define F_IN  512
#define T_LEN 256
#define HID   1024
#define OUTD  128

#define N_CHAINS (BATCH * HID)                  // 32768 LIF chains per layer

// Output layout (floats): spikes0, spikes1, readouts0, readouts1, voltages0, voltages1, counts[2]
#define SOFF0 ((size_t)0)
#define SOFF1 ((size_t)8388608)
#define ROFF0 ((size_t)16777216)
#define ROFF1 ((size_t)17825792)
#define VOFF0 ((size_t)18874368)
#define VOFF1 ((size_t)27262976)
#define CNTOFF ((size_t)35651584)

// ---------------- device scratch ----------------
__device__ float  g_s [(size_t)BATCH * 3 * HID  * T_LEN];    // hidden plane sums (100.7MB)
__device__ float  g_sr[(size_t)BATCH * 3 * OUTD * T_LEN];    // readout plane sums (12.6MB)
__device__ __half g_bT[(size_t)BATCH * T_LEN * HID];         // transposed f16 B operand (reused)
__device__ __half g_w1h [3 * HID * F_IN];                    // W1 digit planes
__device__ __half g_w2r1[3 * HID * HID + 3 * OUTD * HID];    // W2 planes ++ R1 planes (stacked)
__device__ __half g_r2h [3 * OUTD * HID];                    // R2 digit planes
__device__ unsigned long long g_cnt[2];

// ---------------- baseline-PTX helpers (valid on compute_103) ----------------
__device__ __forceinline__ uint32_t smem_u32(const void* p) {
    uint32_t a;
    asm("{ .reg .u64 t; cvta.to.shared.u64 t, %1; cvt.u32.u64 %0, t; }" : "=r"(a) : "l"(p));
    return a;
}

__device__ __forceinline__ void cp_async16(uint32_t dst, const void* src) {
    asm volatile("cp.async.ca.shared.global [%0], [%1], 16;" :: "r"(dst), "l"(src));
}
#define CP_COMMIT() asm volatile("cp.async.commit_group;" ::: "memory")
#define CP_WAIT0()  asm volatile("cp.async.wait_group 0;" ::: "memory")

__device__ __forceinline__ void ldsm_x4(uint32_t r[4], uint32_t addr) {
    asm volatile("ldmatrix.sync.aligned.m8n8.x4.shared.b16 {%0,%1,%2,%3}, [%4];"
        : "=r"(r[0]), "=r"(r[1]), "=r"(r[2]), "=r"(r[3]) : "r"(addr));
}

// f16 MMA with f32 accumulate. Exact for small-integer operands (all sums < 2^24).
__device__ __forceinline__ void mma_f16(float* d, const uint32_t* a, uint32_t b0, uint32_t b1) {
    asm volatile(
        "mma.sync.aligned.m16n8k16.row.col.f32.f16.f16.f32 "
        "{%0,%1,%2,%3}, {%4,%5,%6,%7}, {%8,%9}, {%0,%1,%2,%3};"
        : "+f"(d[0]), "+f"(d[1]), "+f"(d[2]), "+f"(d[3])
        : "r"(a[0]), "r"(a[1]), "r"(a[2]), "r"(a[3]), "r"(b0), "r"(b1));
}

// ---------------- small kernels ----------------
__global__ void init_counts_kernel() { g_cnt[0] = 0ull; g_cnt[1] = 0ull; }

// Exact 3-digit balanced base-2048 fixed-point split at scale 2^33.
// q = rint(w*2^33); q = c0*2^22 + c1*2^11 + c2 exactly, |ci| <= 1024 (exact in fp16).
__global__ void wprep_kernel(const float* __restrict__ W, __half* __restrict__ out, int n) {
    for (int i = blockIdx.x * blockDim.x + threadIdx.x; i < n; i += gridDim.x * blockDim.x) {
        double wd = (double)W[i] * 8589934592.0;   // 2^33, exact
        long long q = llrint(wd);
        long long c0 = (q + (1LL << 21)) >> 22;
        long long r  = q - (c0 << 22);
        long long c1 = (r + (1LL << 10)) >> 11;
        long long c2 = r - (c1 << 11);
        out[i]         = __int2half_rn((int)c0);
        out[n + i]     = __int2half_rn((int)c1);
        out[2 * n + i] = __int2half_rn((int)c2);
    }
}

// in: fp32 [B, F, T] (values exactly 0/1) -> out: f16 [B, T, F]
__global__ void transpose_h_kernel(const float* __restrict__ in,
                                   __half* __restrict__ outT, int F) {
    __shared__ float tile[32][33];
    const int b = blockIdx.z;
    const int t0 = blockIdx.x * 32, f0 = blockIdx.y * 32;
    const float* inp = in + ((size_t)b * F + f0) * T_LEN + t0;
#pragma unroll
    for (int i = 0; i < 4; i++)
        tile[threadIdx.y + i * 8][threadIdx.x] = inp[(size_t)(threadIdx.y + i * 8) * T_LEN + threadIdx.x];
    __syncthreads();
    __half* op = outT + ((size_t)b * T_LEN + t0) * F + f0;
    const __half one = __float2half(1.0f), zero = __float2half(0.0f);
#pragma unroll
    for (int i = 0; i < 4; i++)
        op[(size_t)(threadIdx.y + i * 8) * F + threadIdx.x] =
            (tile[threadIdx.x][threadIdx.y + i * 8] >= 0.5f) ? one : zero;
}

// ---------------- exact f16 tensor-core plane-GEMM (stacked planes in M) ----------------
// S[b, row, t] = sum_k A[row, k] * Bt[b, t, k]
// A: [Mtot][K] f16 digits.  Bt: [B][T_LEN][K] f16 (0/1).  All partial sums integers < 2^24: exact.
// Rows < Mhid -> Sh [B][Mhid][T]; remaining Mr rows -> Sr [B][Mr][T].
// CTA tile 128(M) x 128(N), K chunk 64; 8 warps = 4(M) x 2(N), warp tile 32x64.
// smem rows: 128B data + 16B pad = 144B -> conflict-free ldmatrix.
__global__ __launch_bounds__(256, 2)
void hmma_gemm_kernel(const __half* __restrict__ A,
                      const __half* __restrict__ Bt,
                      float* __restrict__ Sh, float* __restrict__ Sr,
                      int Mhid, int Mr, int K)
{
    constexpr int ROWB  = 144;
    constexpr int BOFF  = 128 * ROWB;            // 18432
    constexpr int STAGE = 2 * BOFF;              // 36864

    extern __shared__ __align__(16) char smem[];
    const uint32_t uS = smem_u32(smem);

    const int tid  = threadIdx.x;
    const int wid  = tid >> 5;
    const int lane = tid & 31;
    const int wm   = wid & 3;          // warp m-group (32 rows)
    const int wn   = wid >> 2;         // warp n-group (64 cols)

    const int m0 = blockIdx.y * 128;
    const int n0 = blockIdx.x * 128;
    const int b  = blockIdx.z;

    const __half* Brow = Bt + ((size_t)b * T_LEN + n0) * K;

    // A and B tiles: each 128 rows x 8 16B-chunks = 1024 -> 4 per thread.
    int cr[4], cq[4];
#pragma unroll
    for (int u = 0; u < 4; u++) { cr[u] = (tid + u * 256) >> 3; cq[u] = (tid + u * 256) & 7; }

    const uint32_t lmoff = (uint32_t)((lane & 15) * ROWB + (lane >> 4) * 16);

    float acc[2][8][4];
#pragma unroll
    for (int ii = 0; ii < 2; ii++)
#pragma unroll
        for (int jj = 0; jj < 8; jj++)
#pragma unroll
            for (int r = 0; r < 4; r++) acc[ii][jj][r] = 0.0f;

    const int NKC = K / 64;

    // ---- prologue: stage 0 ----
#pragma unroll
    for (int u = 0; u < 4; u++) {
        cp_async16(uS + cr[u] * ROWB + cq[u] * 16,
                   A + (size_t)(m0 + cr[u]) * K + cq[u] * 8);
        cp_async16(uS + BOFF + cr[u] * ROWB + cq[u] * 16,
                   Brow + (size_t)cr[u] * K + cq[u] * 8);
    }
    CP_COMMIT();

    for (int kc = 0; kc < NKC; kc++) {
        const uint32_t cur = (uint32_t)(kc & 1) * STAGE;
        CP_WAIT0();
        __syncthreads();

        if (kc + 1 < NKC) {
            const uint32_t nxt = (uint32_t)((kc + 1) & 1) * STAGE;
            const int kB = (kc + 1) * 64;
#pragma unroll
            for (int u = 0; u < 4; u++) {
                cp_async16(uS + nxt + cr[u] * ROWB + cq[u] * 16,
                           A + (size_t)(m0 + cr[u]) * K + kB + cq[u] * 8);
                cp_async16(uS + nxt + BOFF + cr[u] * ROWB + cq[u] * 16,
                           Brow + (size_t)cr[u] * K + kB + cq[u] * 8);
            }
            CP_COMMIT();
        }

        // 4 k16-steps per 64-element chunk (32B each)
#pragma unroll
        for (int ks = 0; ks < 4; ks++) {
            const uint32_t koff = cur + (uint32_t)(ks * 32) + lmoff;

            uint32_t bf[4][4];
#pragma unroll
            for (int j2 = 0; j2 < 4; j2++)
                ldsm_x4(bf[j2], uS + BOFF + (uint32_t)((wn * 64 + j2 * 16) * ROWB) + koff);

#pragma unroll
            for (int ii = 0; ii < 2; ii++) {
                uint32_t af[4];
                ldsm_x4(af, uS + (uint32_t)((wm * 32 + ii * 16) * ROWB) + koff);
#pragma unroll
                for (int j2 = 0; j2 < 4; j2++) {
                    mma_f16(acc[ii][2 * j2 + 0], af, bf[j2][0], bf[j2][2]);
                    mma_f16(acc[ii][2 * j2 + 1], af, bf[j2][1], bf[j2][3]);
                }
            }
        }
        __syncthreads();
    }

    // ---- epilogue: write exact plane sums (fp32 integers) ----
    float* dst;
    if (m0 < Mhid) dst = Sh + ((size_t)b * Mhid + m0) * T_LEN;
    else           dst = Sr + ((size_t)b * Mr + (m0 - Mhid)) * T_LEN;

#pragma unroll
    for (int ii = 0; ii < 2; ii++) {
        const int rloc = wm * 32 + ii * 16 + (lane >> 2);
        float* d0 = dst + (size_t)rloc * T_LEN + n0 + wn * 64 + (lane & 3) * 2;
#pragma unroll
        for (int jj = 0; jj < 8; jj++) {
            *(float2*)(d0 + jj * 8)             = make_float2(acc[ii][jj][0], acc[ii][jj][1]);
            *(float2*)(d0 + 8 * T_LEN + jj * 8) = make_float2(acc[ii][jj][2], acc[ii][jj][3]);
        }
    }
}

// ---------------- digit fold (3 planes, base 2048, scale 2^33; exact in double) ----------------
__device__ __forceinline__ float fold3(float a, float b, float c) {
    return (float)(((double)a * 4194304.0 + (double)b * 2048.0 + (double)c)
                   * (1.0 / 8589934592.0));
}

// ---------------- LIF with on-the-fly digit fold ----------------
__global__ __launch_bounds__(256)
void lif_fold_kernel(float* __restrict__ v_out, float* __restrict__ s_out, int layer)
{
    const int idx = blockIdx.x * blockDim.x + threadIdx.x;   // chain = b*HID + h
    const int b = idx / HID, h = idx % HID;
    const float4* __restrict__ p0 = (const float4*)(g_s + ((size_t)b * 3 * HID + h) * T_LEN);
    const float4* __restrict__ p1 = (const float4*)(g_s + ((size_t)b * 3 * HID + HID + h) * T_LEN);
    const float4* __restrict__ p2 = (const float4*)(g_s + ((size_t)b * 3 * HID + 2 * HID + h) * T_LEN);
    float4* __restrict__ vp4 = (float4*)(v_out + (size_t)idx * T_LEN);
    float4* __restrict__ sp4 = (float4*)(s_out + (size_t)idx * T_LEN);

    float cur = 0.0f, volt = 0.0f;
    unsigned cnt = 0;

#pragma unroll 4
    for (int t4 = 0; t4 < T_LEN / 4; t4++) {
        const float4 a = p0[t4], bb = p1[t4], c = p2[t4];
        float4 z;
        z.x = fold3(a.x, bb.x, c.x);
        z.y = fold3(a.y, bb.y, c.y);
        z.z = fold3(a.z, bb.z, c.z);
        z.w = fold3(a.w, bb.w, c.w);
        float4 v, s;
        cur = 0.75f * cur + z.x;  volt = 0.97f * volt + cur;  v.x = volt;
        { bool sp = volt >= 1.25f; s.x = sp ? 1.0f : 0.0f; cnt += (unsigned)sp; if (sp) volt = 0.0f; }
        cur = 0.75f * cur + z.y;  volt = 0.97f * volt + cur;  v.y = volt;
        { bool sp = volt >= 1.25f; s.y = sp ? 1.0f : 0.0f; cnt += (unsigned)sp; if (sp) volt = 0.0f; }
        cur = 0.75f * cur + z.z;  volt = 0.97f * volt + cur;  v.z = volt;
        { bool sp = volt >= 1.25f; s.z = sp ? 1.0f : 0.0f; cnt += (unsigned)sp; if (sp) volt = 0.0f; }
        cur = 0.75f * cur + z.w;  volt = 0.97f * volt + cur;  v.w = volt;
        { bool sp = volt >= 1.25f; s.w = sp ? 1.0f : 0.0f; cnt += (unsigned)sp; if (sp) volt = 0.0f; }
        vp4[t4] = v;
        sp4[t4] = s;
    }

    __shared__ unsigned red[256];
    red[threadIdx.x] = cnt;
    __syncthreads();
#pragma unroll
    for (int off = 128; off > 0; off >>= 1) {
        if (threadIdx.x < off) red[threadIdx.x] += red[threadIdx.x + off];
        __syncthreads();
    }
    if (threadIdx.x == 0)
        atomicAdd(&g_cnt[layer], (unsigned long long)red[0]);
}

// fold readout planes: Sr [B][3*OUTD][T] -> r [B][OUTD][T]
__global__ __launch_bounds__(256)
void fold_readout_kernel(float* __restrict__ rout)
{
    const int i = blockIdx.x * blockDim.x + threadIdx.x;   // over B*OUTD*T/4
    const int per = OUTD * T_LEN / 4;
    const int b = i / per, rem = i % per;
    const float4* base = (const float4*)(g_sr + (size_t)b * 3 * OUTD * T_LEN);
    const float4 a  = base[0 * per + rem];
    const float4 bb = base[1 * per + rem];
    const float4 c  = base[2 * per + rem];
    float4 r;
    r.x = fold3(a.x, bb.x, c.x);
    r.y = fold3(a.y, bb.y, c.y);
    r.z = fold3(a.z, bb.z, c.z);
    r.w = fold3(a.w, bb.w, c.w);
    ((float4*)(rout + (size_t)b * OUTD * T_LEN))[rem] = r;
}

__global__ void finalize_counts_kernel(float* __restrict__ out)
{
    const double total = (double)((size_t)BATCH * HID * T_LEN);
    out[0] = (float)((double)g_cnt[0] / total);
    out[1] = (float)((double)g_cnt[1] / total);
}

// ---------------- launch ----------------
extern "C" void kernel_launch(void* const* d_in, const int* in_sizes, int n_in,
                              void* d_out, int out_size)
{
    const float* spike = (const float*)d_in[0]; // [32, 512, 256]
    const float* W1    = (const float*)d_in[1]; // [1024, 512]
    const float* W2    = (const float*)d_in[2]; // [1024, 1024]
    const float* R1    = (const float*)d_in[3]; // [128, 1024]
    const float* R2    = (const float*)d_in[4]; // [128, 1024]
    float* out = (float*)d_out;

    float *sptr, *srptr;
    __half *bT, *w1h, *w2r1, *r2h;
    cudaGetSymbolAddress((void**)&sptr,  g_s);
    cudaGetSymbolAddress((void**)&srptr, g_sr);
    cudaGetSymbolAddress((void**)&bT,    g_bT);
    cudaGetSymbolAddress((void**)&w1h,   g_w1h);
    cudaGetSymbolAddress((void**)&w2r1,  g_w2r1);
    cudaGetSymbolAddress((void**)&r2h,   g_r2h);

    float* s0 = out + SOFF0;
    float* s1 = out + SOFF1;
    float* r0 = out + ROFF0;
    float* r1 = out + ROFF1;
    float* v0 = out + VOFF0;
    float* v1 = out + VOFF1;

    const int SMEM = 2 * 36864;   // 73728
    cudaFuncSetAttribute(hmma_gemm_kernel, cudaFuncAttributeMaxDynamicSharedMemorySize, SMEM);

    init_counts_kernel<<<1, 1>>>();

    // Weight digit-plane prep (deterministic, every call)
    wprep_kernel<<<256, 256>>>(W1, w1h, HID * F_IN);
    wprep_kernel<<<256, 256>>>(W2, w2r1, HID * HID);
    wprep_kernel<<<128, 256>>>(R1, w2r1 + 3 * HID * HID, OUTD * HID);
    wprep_kernel<<<128, 256>>>(R2, r2h, OUTD * HID);

    // x^T f16
    transpose_h_kernel<<<dim3(T_LEN / 32, F_IN / 32, BATCH), dim3(32, 8)>>>(spike, bT, F_IN);

    // Layer 1 synapse plane sums: S = W1planes @ x  (M=3072, K=512)
    hmma_gemm_kernel<<<dim3(T_LEN / 128, 3 * HID / 128, BATCH), 256, SMEM>>>(
        w1h, bT, sptr, srptr, 3 * HID, 0, F_IN);
    lif_fold_kernel<<<N_CHAINS / 256, 256>>>(v0, s0, 0);

    // s0^T f16
    transpose_h_kernel<<<dim3(T_LEN / 32, HID / 32, BATCH), dim3(32, 8)>>>(s0, bT, HID);

    // Layer 2 synapse + readout 1 in ONE stacked GEMM (M = 3072 + 384 = 3456, K=1024)
    hmma_gemm_kernel<<<dim3(T_LEN / 128, (3 * HID + 3 * OUTD) / 128, BATCH), 256, SMEM>>>(
        w2r1, bT, sptr, srptr, 3 * HID, 3 * OUTD, HID);

    lif_fold_kernel<<<N_CHAINS / 256, 256>>>(v1, s1, 1);
    fold_readout_kernel<<<(BATCH * OUTD * T_LEN / 4) / 256, 256>>>(r0);

    // s1^T f16 ; readout 2 (M=384, K=1024)
    transpose_h_kernel<<<dim3(T_LEN / 32, HID / 32, BATCH), dim3(32, 8)>>>(s1, bT, HID);
    hmma_gemm_kernel<<<dim3(T_LEN / 128, 3 * OUTD / 128, BATCH), 256, SMEM>>>(
        r2h, bT, sptr, srptr, 0, 3 * OUTD, HID);
    fold_readout_kernel<<<(BATCH * OUTD * T_LEN / 4) / 256, 256>>>(r1);

    finalize_counts_kernel<<<1, 1>>>(out + CNTOFF);
}